// round 3
// baseline (speedup 1.0000x reference)
#include <cuda_runtime.h>
#include <cuda_bf16.h>
#include <stdint.h>

// Problem constants: B=8, S=2048 -> M=16384 rows; LATENT = EDIM = 512; NE = 8192.
#define MROWS 16384
#define KDIM  512
#define NEMB  8192
#define NSPLIT 8
#define SLICE (NEMB / NSPLIT)      // 1024 codes per block-column
#define CAP_S 16                   // candidate slots per (row, slice)
#define CAND_STRIDE (NSPLIT * CAP_S)   // 128 slots per row
#define EPS 4e-3f

// ---------------- scratch (static __device__ arrays; no allocs) -------------
__device__ float                        g_zf[(size_t)MROWS * KDIM];
__device__ __align__(16) __nv_bfloat16  g_zfb[(size_t)MROWS * KDIM];
__device__ float                        g_embn[(size_t)NEMB * KDIM];
__device__ __align__(16) __nv_bfloat16  g_embnb[(size_t)NEMB * KDIM];
__device__ int2                         g_cand[(size_t)MROWS * CAND_STRIDE]; // {code, score bits}
__device__ int                          g_ccnt[MROWS * NSPLIT];
__device__ int                          g_idx[MROWS];

// ---------------- helpers ---------------------------------------------------
__device__ __forceinline__ unsigned mono_f2u(float f) {
    int b = __float_as_int(f);
    return (b >= 0) ? ((unsigned)b | 0x80000000u) : ~(unsigned)b;
}
__device__ __forceinline__ float mono_u2f(unsigned u) {
    return (u & 0x80000000u) ? __int_as_float((int)(u ^ 0x80000000u))
                             : __int_as_float((int)~u);
}
__device__ __forceinline__ void cpasync16(uint32_t dst, const void* src) {
    asm volatile("cp.async.cg.shared.global [%0], [%1], 16;\n" :: "r"(dst), "l"(src));
}
__device__ __forceinline__ void cpasync_commit() {
    asm volatile("cp.async.commit_group;\n");
}
template<int N>
__device__ __forceinline__ void cpasync_wait() {
    asm volatile("cp.async.wait_group %0;\n" :: "n"(N));
}
__device__ __forceinline__ void ldmatrix_x4(unsigned& r0, unsigned& r1, unsigned& r2,
                                            unsigned& r3, uint32_t addr) {
    asm volatile("ldmatrix.sync.aligned.m8n8.x4.shared.b16 {%0,%1,%2,%3}, [%4];\n"
                 : "=r"(r0), "=r"(r1), "=r"(r2), "=r"(r3) : "r"(addr));
}
__device__ __forceinline__ void mma_bf16(float* c, const unsigned* a, const unsigned* b) {
    asm volatile(
        "mma.sync.aligned.m16n8k16.row.col.f32.bf16.bf16.f32 "
        "{%0,%1,%2,%3}, {%4,%5,%6,%7}, {%8,%9}, {%0,%1,%2,%3};\n"
        : "+f"(c[0]), "+f"(c[1]), "+f"(c[2]), "+f"(c[3])
        : "r"(a[0]), "r"(a[1]), "r"(a[2]), "r"(a[3]), "r"(b[0]), "r"(b[1]));
}

// ---------------- row L2 normalize: emb -> g_embn / g_embnb -----------------
__global__ void norm_emb_kernel(const float* __restrict__ emb) {
    int row = blockIdx.x;
    int t = threadIdx.x;   // 128 threads, 512 floats per row
    float4 v = reinterpret_cast<const float4*>(emb + (size_t)row * KDIM)[t];
    float ss = v.x*v.x + v.y*v.y + v.z*v.z + v.w*v.w;
    #pragma unroll
    for (int o = 16; o > 0; o >>= 1) ss += __shfl_xor_sync(0xffffffffu, ss, o);
    __shared__ float ws[4];
    if ((t & 31) == 0) ws[t >> 5] = ss;
    __syncthreads();
    float s = 1.0f / fmaxf(sqrtf(ws[0] + ws[1] + ws[2] + ws[3]), 1e-12f);
    float4 o4 = make_float4(v.x*s, v.y*s, v.z*s, v.w*s);
    reinterpret_cast<float4*>(g_embn + (size_t)row * KDIM)[t] = o4;
    __nv_bfloat162* ob = reinterpret_cast<__nv_bfloat162*>(g_embnb + (size_t)row * KDIM);
    ob[t*2]     = __floats2bfloat162_rn(o4.x, o4.y);
    ob[t*2 + 1] = __floats2bfloat162_rn(o4.z, o4.w);
}

// ---------------- row L2 normalize: g_zf (in place) -> g_zfb ----------------
__global__ void norm_zf_kernel() {
    int row = blockIdx.x;
    int t = threadIdx.x;
    float4 v = reinterpret_cast<const float4*>(g_zf + (size_t)row * KDIM)[t];
    float ss = v.x*v.x + v.y*v.y + v.z*v.z + v.w*v.w;
    #pragma unroll
    for (int o = 16; o > 0; o >>= 1) ss += __shfl_xor_sync(0xffffffffu, ss, o);
    __shared__ float ws[4];
    if ((t & 31) == 0) ws[t >> 5] = ss;
    __syncthreads();
    float s = 1.0f / fmaxf(sqrtf(ws[0] + ws[1] + ws[2] + ws[3]), 1e-12f);
    float4 o4 = make_float4(v.x*s, v.y*s, v.z*s, v.w*s);
    reinterpret_cast<float4*>(g_zf + (size_t)row * KDIM)[t] = o4;
    __nv_bfloat162* ob = reinterpret_cast<__nv_bfloat162*>(g_zfb + (size_t)row * KDIM);
    ob[t*2]     = __floats2bfloat162_rn(o4.x, o4.y);
    ob[t*2 + 1] = __floats2bfloat162_rn(o4.z, o4.w);
}

// ---------------- fp32 SGEMM: C[m][n] = sum_k A[m][k]*B[n][k] + bias[n] -----
template<bool GATHER>
__global__ void __launch_bounds__(256) sgemm512(const float* __restrict__ Aext,
                                                const float* __restrict__ Bw,
                                                const float* __restrict__ bias,
                                                float* __restrict__ Cext) {
    constexpr int BM = 128, BN = 128, BK = 16;
    __shared__ float As[BK][BM];
    __shared__ float Bs[BK][BN];
    const int tid = threadIdx.x;
    const int tx = tid & 15, ty = tid >> 4;
    const int m0 = blockIdx.y * BM, n0 = blockIdx.x * BN;
    const int lr = tid >> 1;
    const int lc = (tid & 1) << 3;
    const float* Arow;
    if (GATHER) Arow = g_embn + (size_t)g_idx[m0 + lr] * KDIM;
    else        Arow = Aext + (size_t)(m0 + lr) * KDIM;
    const float* Brow = Bw + (size_t)(n0 + lr) * KDIM;
    float* C = GATHER ? Cext : g_zf;

    float acc[8][8];
    #pragma unroll
    for (int i = 0; i < 8; ++i)
        #pragma unroll
        for (int j = 0; j < 8; ++j) acc[i][j] = 0.0f;

    for (int k0 = 0; k0 < KDIM; k0 += BK) {
        float4 a0 = *reinterpret_cast<const float4*>(Arow + k0 + lc);
        float4 a1 = *reinterpret_cast<const float4*>(Arow + k0 + lc + 4);
        float4 b0 = *reinterpret_cast<const float4*>(Brow + k0 + lc);
        float4 b1 = *reinterpret_cast<const float4*>(Brow + k0 + lc + 4);
        As[lc+0][lr] = a0.x; As[lc+1][lr] = a0.y; As[lc+2][lr] = a0.z; As[lc+3][lr] = a0.w;
        As[lc+4][lr] = a1.x; As[lc+5][lr] = a1.y; As[lc+6][lr] = a1.z; As[lc+7][lr] = a1.w;
        Bs[lc+0][lr] = b0.x; Bs[lc+1][lr] = b0.y; Bs[lc+2][lr] = b0.z; Bs[lc+3][lr] = b0.w;
        Bs[lc+4][lr] = b1.x; Bs[lc+5][lr] = b1.y; Bs[lc+6][lr] = b1.z; Bs[lc+7][lr] = b1.w;
        __syncthreads();
        #pragma unroll
        for (int kk = 0; kk < BK; ++kk) {
            float a[8], b[8];
            *reinterpret_cast<float4*>(a)     = *reinterpret_cast<const float4*>(&As[kk][ty*8]);
            *reinterpret_cast<float4*>(a + 4) = *reinterpret_cast<const float4*>(&As[kk][ty*8 + 4]);
            *reinterpret_cast<float4*>(b)     = *reinterpret_cast<const float4*>(&Bs[kk][tx*8]);
            *reinterpret_cast<float4*>(b + 4) = *reinterpret_cast<const float4*>(&Bs[kk][tx*8 + 4]);
            #pragma unroll
            for (int i = 0; i < 8; ++i)
                #pragma unroll
                for (int j = 0; j < 8; ++j) acc[i][j] += a[i] * b[j];
        }
        __syncthreads();
    }

    float bb[8];
    *reinterpret_cast<float4*>(bb)     = *reinterpret_cast<const float4*>(bias + n0 + tx*8);
    *reinterpret_cast<float4*>(bb + 4) = *reinterpret_cast<const float4*>(bias + n0 + tx*8 + 4);
    #pragma unroll
    for (int i = 0; i < 8; ++i) {
        int m = m0 + ty*8 + i;
        float* cp = C + (size_t)m * KDIM + n0 + tx*8;
        *reinterpret_cast<float4*>(cp) =
            make_float4(acc[i][0]+bb[0], acc[i][1]+bb[1], acc[i][2]+bb[2], acc[i][3]+bb[3]);
        *reinterpret_cast<float4*>(cp + 4) =
            make_float4(acc[i][4]+bb[4], acc[i][5]+bb[5], acc[i][6]+bb[6], acc[i][7]+bb[7]);
    }
}

// ---------------- distance GEMM (bf16 HMMA) + candidate collection ----------
// Grid (MROWS/128, NSPLIT). Block: 128 rows x 1024 codes, 64-code tiles.
// Epilogue scans accumulator registers directly: per-row running max in shared
// (flipped-uint atomicMax), eps-filtered appends {code, bf16score} to g_cand.
__global__ void __launch_bounds__(256) dist_cand_kernel() {
    constexpr int BM = 128, BN = 64, BK = 32, LDS = 40; // pad 8 elems -> conflict-free
    __shared__ __align__(16) __nv_bfloat16 As[2][BM * LDS];
    __shared__ __align__(16) __nv_bfloat16 Bs[2][BN * LDS];
    __shared__ unsigned s_best[BM];
    __shared__ int      s_cnt[BM];

    const int tid = threadIdx.x;
    const int lane = tid & 31, wid = tid >> 5;
    const int g = lane >> 2, tg = lane & 3;
    const int wm = (wid >> 1) * 32;   // 4 warps in m
    const int wn = (wid & 1) * 32;    // 2 warps in n
    const int m0 = blockIdx.x * BM;
    const int slice = blockIdx.y;
    const int n0 = slice * SLICE;

    if (tid < BM) { s_best[tid] = mono_f2u(-3.4e38f); s_cnt[tid] = 0; }

    // cp.async chunk mapping
    const int ar0 = tid >> 2,        ac = (tid & 3) << 3;  // A: 2 chunks (rows tid>>2, +64)
    const int br  = tid >> 2;                              // B: 1 chunk
    uint32_t sA[2], sB[2];
    #pragma unroll
    for (int b = 0; b < 2; ++b) {
        sA[b] = (uint32_t)__cvta_generic_to_shared(&As[b][0]);
        sB[b] = (uint32_t)__cvta_generic_to_shared(&Bs[b][0]);
    }
    // ldmatrix lane addresses (element offsets within a buffer)
    const int aRowA = wm + (lane & 15);            // + ms*16
    const int aColA = ((lane >> 4) << 3);          // + kk
    const int aRowB = wn + ((lane >> 4) << 3) + (lane & 7);   // + p*16
    const int aColB = (((lane >> 3) & 1) << 3);    // + kk
    __syncthreads();

    for (int nt = 0; nt < SLICE / BN; ++nt) {
        float acc[2][4][4];
        #pragma unroll
        for (int i = 0; i < 2; ++i)
            #pragma unroll
            for (int j = 0; j < 4; ++j)
                #pragma unroll
                for (int q = 0; q < 4; ++q) acc[i][j][q] = 0.0f;

        // prologue: load kt=0 into buffer 0
        {
            const int kt = 0;
            cpasync16(sA[0] + (uint32_t)(ar0 * LDS + ac) * 2,
                      g_zfb + (size_t)(m0 + ar0) * KDIM + kt * BK + ac);
            cpasync16(sA[0] + (uint32_t)((ar0 + 64) * LDS + ac) * 2,
                      g_zfb + (size_t)(m0 + ar0 + 64) * KDIM + kt * BK + ac);
            cpasync16(sB[0] + (uint32_t)(br * LDS + ac) * 2,
                      g_embnb + (size_t)(n0 + nt * BN + br) * KDIM + kt * BK + ac);
            cpasync_commit();
        }

        for (int kt = 0; kt < KDIM / BK; ++kt) {
            const int cur = kt & 1;
            if (kt < KDIM / BK - 1) {
                const int nx = 1 - cur, ktn = kt + 1;
                cpasync16(sA[nx] + (uint32_t)(ar0 * LDS + ac) * 2,
                          g_zfb + (size_t)(m0 + ar0) * KDIM + ktn * BK + ac);
                cpasync16(sA[nx] + (uint32_t)((ar0 + 64) * LDS + ac) * 2,
                          g_zfb + (size_t)(m0 + ar0 + 64) * KDIM + ktn * BK + ac);
                cpasync16(sB[nx] + (uint32_t)(br * LDS + ac) * 2,
                          g_embnb + (size_t)(n0 + nt * BN + br) * KDIM + ktn * BK + ac);
                cpasync_commit();
                cpasync_wait<1>();
            } else {
                cpasync_wait<0>();
            }
            __syncthreads();

            #pragma unroll
            for (int kk = 0; kk < BK; kk += 16) {
                unsigned a[2][4], b[4][2];
                #pragma unroll
                for (int ms = 0; ms < 2; ++ms) {
                    uint32_t addr = sA[cur] + (uint32_t)((aRowA + ms*16) * LDS + aColA + kk) * 2;
                    ldmatrix_x4(a[ms][0], a[ms][1], a[ms][2], a[ms][3], addr);
                }
                #pragma unroll
                for (int p = 0; p < 2; ++p) {
                    uint32_t addr = sB[cur] + (uint32_t)((aRowB + p*16) * LDS + aColB + kk) * 2;
                    ldmatrix_x4(b[2*p][0], b[2*p][1], b[2*p+1][0], b[2*p+1][1], addr);
                }
                #pragma unroll
                for (int ms = 0; ms < 2; ++ms)
                    #pragma unroll
                    for (int ns = 0; ns < 4; ++ns)
                        mma_bf16(acc[ms][ns], a[ms], b[ns]);
            }
            __syncthreads();
        }

        // ---- epilogue: running max + eps-filtered candidate append ----
        #pragma unroll
        for (int ms = 0; ms < 2; ++ms) {
            float mA = -3.4e38f, mB = -3.4e38f;   // rows wm+ms*16+g and +8
            #pragma unroll
            for (int ns = 0; ns < 4; ++ns) {
                mA = fmaxf(mA, fmaxf(acc[ms][ns][0], acc[ms][ns][1]));
                mB = fmaxf(mB, fmaxf(acc[ms][ns][2], acc[ms][ns][3]));
            }
            #pragma unroll
            for (int o = 1; o <= 2; o <<= 1) {
                mA = fmaxf(mA, __shfl_xor_sync(0xffffffffu, mA, o));
                mB = fmaxf(mB, __shfl_xor_sync(0xffffffffu, mB, o));
            }
            if (tg == 0) {
                atomicMax(&s_best[wm + ms*16 + g],     mono_f2u(mA));
                atomicMax(&s_best[wm + ms*16 + g + 8], mono_f2u(mB));
            }
        }
        __syncthreads();
        #pragma unroll
        for (int ms = 0; ms < 2; ++ms) {
            const int rA = wm + ms*16 + g, rB = rA + 8;
            const float thA = mono_u2f(s_best[rA]) - EPS;
            const float thB = mono_u2f(s_best[rB]) - EPS;
            #pragma unroll
            for (int ns = 0; ns < 4; ++ns) {
                const int code = n0 + nt * BN + wn + ns*8 + tg*2;
                #pragma unroll
                for (int h = 0; h < 2; ++h) {
                    float vA = acc[ms][ns][h];
                    if (vA > thA) {
                        int pos = atomicAdd(&s_cnt[rA], 1);
                        if (pos < CAP_S)
                            g_cand[(size_t)(m0 + rA) * CAND_STRIDE + slice * CAP_S + pos] =
                                make_int2(code + h, __float_as_int(vA));
                    }
                    float vB = acc[ms][ns][2 + h];
                    if (vB > thB) {
                        int pos = atomicAdd(&s_cnt[rB], 1);
                        if (pos < CAP_S)
                            g_cand[(size_t)(m0 + rB) * CAND_STRIDE + slice * CAP_S + pos] =
                                make_int2(code + h, __float_as_int(vB));
                    }
                }
            }
        }
        // racing atomicMax from faster warps only raises thresholds, which is
        // safe (candidate set stays a superset of the argmax); no extra bar.
    }
    __syncthreads();
    if (tid < BM) g_ccnt[(m0 + tid) * NSPLIT + slice] = s_cnt[tid];
}

// ---------------- exact fp32 rescore of candidates -> argmax index ----------
__global__ void __launch_bounds__(256) rescore_kernel() {
    const int wid = threadIdx.x >> 5;
    const int lane = threadIdx.x & 31;
    const int row = blockIdx.x * 8 + wid;
    const float* zr = g_zf + (size_t)row * KDIM;
    float zv[16];
    #pragma unroll
    for (int i = 0; i < 16; ++i) zv[i] = zr[lane + 32*i];

    int cnt_l = (lane < NSPLIT) ? g_ccnt[row * NSPLIT + lane] : 0;
    bool ovf = __ballot_sync(0xffffffffu, cnt_l > CAP_S) != 0;

    float best = -3.4e38f;
    int bi = NEMB;
    if (!ovf) {
        const int2* cr = g_cand + (size_t)row * CAND_STRIDE;
        // pass 1: global bf16-score max over all candidates
        float ms = -3.4e38f;
        for (int s = 0; s < NSPLIT; ++s) {
            int c = __shfl_sync(0xffffffffu, cnt_l, s);
            for (int j = lane; j < c; j += 32)
                ms = fmaxf(ms, __int_as_float(cr[s * CAP_S + j].y));
        }
        #pragma unroll
        for (int o = 16; o > 0; o >>= 1) ms = fmaxf(ms, __shfl_xor_sync(0xffffffffu, ms, o));
        const float th = ms - EPS;
        // pass 2: exact fp32 dot for the few above-threshold candidates
        for (int s = 0; s < NSPLIT; ++s) {
            int c = __shfl_sync(0xffffffffu, cnt_l, s);
            for (int j = 0; j < c; ++j) {
                int2 e = cr[s * CAP_S + j];           // broadcast load
                if (__int_as_float(e.y) <= th) continue;
                const float* er = g_embn + (size_t)e.x * KDIM;
                float sum = 0.0f;
                #pragma unroll
                for (int i = 0; i < 16; ++i) sum += zv[i] * er[lane + 32*i];
                #pragma unroll
                for (int o = 16; o > 0; o >>= 1) sum += __shfl_xor_sync(0xffffffffu, sum, o);
                if (sum > best || (sum == best && e.x < bi)) { best = sum; bi = e.x; }
            }
        }
    } else {
        // overflow fallback: full fp32 scan (statistically never)
        for (int code = 0; code < NEMB; ++code) {
            const float* er = g_embn + (size_t)code * KDIM;
            float sum = 0.0f;
            #pragma unroll
            for (int i = 0; i < 16; ++i) sum += zv[i] * er[lane + 32*i];
            #pragma unroll
            for (int o = 16; o > 0; o >>= 1) sum += __shfl_xor_sync(0xffffffffu, sum, o);
            if (sum > best) { best = sum; bi = code; }
        }
    }
    if (lane == 0) g_idx[row] = bi;
}

// ---------------- write idx (cast to float) to output tail ------------------
__global__ void write_idx_kernel(float* __restrict__ dst, int n) {
    int i = blockIdx.x * blockDim.x + threadIdx.x;
    if (i < n) dst[i] = (float)g_idx[i];
}

// ---------------- launch ----------------------------------------------------
extern "C" void kernel_launch(void* const* d_in, const int* in_sizes, int n_in,
                              void* d_out, int out_size) {
    const float* z     = (const float*)d_in[0];
    // d_in[1] = mask (all true; unused by the reference math)
    const float* W_in  = (const float*)d_in[2];
    const float* b_in  = (const float*)d_in[3];
    const float* W_out = (const float*)d_in[4];
    const float* b_out = (const float*)d_in[5];
    const float* emb   = (const float*)d_in[6];
    float* out = (float*)d_out;

    norm_emb_kernel<<<NEMB, 128>>>(emb);
    sgemm512<false><<<dim3(KDIM/128, MROWS/128), 256>>>(z, W_in, b_in, nullptr);
    norm_zf_kernel<<<MROWS, 128>>>();
    dist_cand_kernel<<<dim3(MROWS/128, NSPLIT), 256>>>();
    rescore_kernel<<<MROWS/8, 256>>>();
    sgemm512<true><<<dim3(KDIM/128, MROWS/128), 256>>>(nullptr, W_out, b_out, out);
    int tail = out_size - MROWS * KDIM;
    if (tail > 0) {
        int n = tail < MROWS ? tail : MROWS;
        write_idx_kernel<<<(n + 255) / 256, 256>>>(out + (size_t)MROWS * KDIM, n);
    }
}

// round 6
// speedup vs baseline: 5.5378x; 5.5378x over previous
#include <cuda_runtime.h>
#include <cuda_bf16.h>
#include <stdint.h>

// Problem constants: B=8, S=2048 -> M=16384 rows; LATENT = EDIM = 512; NE = 8192.
#define MROWS 16384
#define KDIM  512
#define NEMB  8192
#define NSPLIT 8
#define SLICE (NEMB / NSPLIT)      // 1024 codes per block-column
#define CAP_S 48                   // candidate slots per (row, slice); mean ~10
#define CAND_STRIDE (NSPLIT * CAP_S)
#define EPS 4e-3f

// ---------------- scratch (static __device__ arrays; no allocs) -------------
__device__ float                        g_zf[(size_t)MROWS * KDIM];
__device__ __align__(16) __nv_bfloat16  g_zfb[(size_t)MROWS * KDIM];
__device__ float                        g_embn[(size_t)NEMB * KDIM];
__device__ __align__(16) __nv_bfloat16  g_embnb[(size_t)NEMB * KDIM];
__device__ int2                         g_cand[(size_t)MROWS * CAND_STRIDE]; // {code, score bits}
__device__ int                          g_ccnt[MROWS * NSPLIT];
__device__ int                          g_idx[MROWS];

// ---------------- helpers ---------------------------------------------------
__device__ __forceinline__ unsigned mono_f2u(float f) {
    int b = __float_as_int(f);
    return (b >= 0) ? ((unsigned)b | 0x80000000u) : ~(unsigned)b;
}
__device__ __forceinline__ float mono_u2f(unsigned u) {
    return (u & 0x80000000u) ? __int_as_float((int)(u ^ 0x80000000u))
                             : __int_as_float((int)~u);
}
__device__ __forceinline__ void cpasync16(uint32_t dst, const void* src) {
    asm volatile("cp.async.cg.shared.global [%0], [%1], 16;\n" :: "r"(dst), "l"(src));
}
__device__ __forceinline__ void cpasync_commit() {
    asm volatile("cp.async.commit_group;\n");
}
template<int N>
__device__ __forceinline__ void cpasync_wait() {
    asm volatile("cp.async.wait_group %0;\n" :: "n"(N));
}
__device__ __forceinline__ void ldmatrix_x4(unsigned& r0, unsigned& r1, unsigned& r2,
                                            unsigned& r3, uint32_t addr) {
    asm volatile("ldmatrix.sync.aligned.m8n8.x4.shared.b16 {%0,%1,%2,%3}, [%4];\n"
                 : "=r"(r0), "=r"(r1), "=r"(r2), "=r"(r3) : "r"(addr));
}
__device__ __forceinline__ void mma_bf16(float* c, const unsigned* a, const unsigned* b) {
    asm volatile(
        "mma.sync.aligned.m16n8k16.row.col.f32.bf16.bf16.f32 "
        "{%0,%1,%2,%3}, {%4,%5,%6,%7}, {%8,%9}, {%0,%1,%2,%3};\n"
        : "+f"(c[0]), "+f"(c[1]), "+f"(c[2]), "+f"(c[3])
        : "r"(a[0]), "r"(a[1]), "r"(a[2]), "r"(a[3]), "r"(b[0]), "r"(b[1]));
}

// ---------------- row L2 normalize: emb -> g_embn / g_embnb -----------------
__global__ void norm_emb_kernel(const float* __restrict__ emb) {
    int row = blockIdx.x;
    int t = threadIdx.x;   // 128 threads, 512 floats per row
    float4 v = reinterpret_cast<const float4*>(emb + (size_t)row * KDIM)[t];
    float ss = v.x*v.x + v.y*v.y + v.z*v.z + v.w*v.w;
    #pragma unroll
    for (int o = 16; o > 0; o >>= 1) ss += __shfl_xor_sync(0xffffffffu, ss, o);
    __shared__ float ws[4];
    if ((t & 31) == 0) ws[t >> 5] = ss;
    __syncthreads();
    float s = 1.0f / fmaxf(sqrtf(ws[0] + ws[1] + ws[2] + ws[3]), 1e-12f);
    float4 o4 = make_float4(v.x*s, v.y*s, v.z*s, v.w*s);
    reinterpret_cast<float4*>(g_embn + (size_t)row * KDIM)[t] = o4;
    __nv_bfloat162* ob = reinterpret_cast<__nv_bfloat162*>(g_embnb + (size_t)row * KDIM);
    ob[t*2]     = __floats2bfloat162_rn(o4.x, o4.y);
    ob[t*2 + 1] = __floats2bfloat162_rn(o4.z, o4.w);
}

// ---------------- row L2 normalize: g_zf (in place) -> g_zfb ----------------
__global__ void norm_zf_kernel() {
    int row = blockIdx.x;
    int t = threadIdx.x;
    float4 v = reinterpret_cast<const float4*>(g_zf + (size_t)row * KDIM)[t];
    float ss = v.x*v.x + v.y*v.y + v.z*v.z + v.w*v.w;
    #pragma unroll
    for (int o = 16; o > 0; o >>= 1) ss += __shfl_xor_sync(0xffffffffu, ss, o);
    __shared__ float ws[4];
    if ((t & 31) == 0) ws[t >> 5] = ss;
    __syncthreads();
    float s = 1.0f / fmaxf(sqrtf(ws[0] + ws[1] + ws[2] + ws[3]), 1e-12f);
    float4 o4 = make_float4(v.x*s, v.y*s, v.z*s, v.w*s);
    reinterpret_cast<float4*>(g_zf + (size_t)row * KDIM)[t] = o4;
    __nv_bfloat162* ob = reinterpret_cast<__nv_bfloat162*>(g_zfb + (size_t)row * KDIM);
    ob[t*2]     = __floats2bfloat162_rn(o4.x, o4.y);
    ob[t*2 + 1] = __floats2bfloat162_rn(o4.z, o4.w);
}

// ---------------- fp32 SGEMM: C[m][n] = sum_k A[m][k]*B[n][k] + bias[n] -----
template<bool GATHER>
__global__ void __launch_bounds__(256) sgemm512(const float* __restrict__ Aext,
                                                const float* __restrict__ Bw,
                                                const float* __restrict__ bias,
                                                float* __restrict__ Cext) {
    constexpr int BM = 128, BN = 128, BK = 16;
    __shared__ float As[BK][BM];
    __shared__ float Bs[BK][BN];
    const int tid = threadIdx.x;
    const int tx = tid & 15, ty = tid >> 4;
    const int m0 = blockIdx.y * BM, n0 = blockIdx.x * BN;
    const int lr = tid >> 1;
    const int lc = (tid & 1) << 3;
    const float* Arow;
    if (GATHER) Arow = g_embn + (size_t)g_idx[m0 + lr] * KDIM;
    else        Arow = Aext + (size_t)(m0 + lr) * KDIM;
    const float* Brow = Bw + (size_t)(n0 + lr) * KDIM;
    float* C = GATHER ? Cext : g_zf;

    float acc[8][8];
    #pragma unroll
    for (int i = 0; i < 8; ++i)
        #pragma unroll
        for (int j = 0; j < 8; ++j) acc[i][j] = 0.0f;

    for (int k0 = 0; k0 < KDIM; k0 += BK) {
        float4 a0 = *reinterpret_cast<const float4*>(Arow + k0 + lc);
        float4 a1 = *reinterpret_cast<const float4*>(Arow + k0 + lc + 4);
        float4 b0 = *reinterpret_cast<const float4*>(Brow + k0 + lc);
        float4 b1 = *reinterpret_cast<const float4*>(Brow + k0 + lc + 4);
        As[lc+0][lr] = a0.x; As[lc+1][lr] = a0.y; As[lc+2][lr] = a0.z; As[lc+3][lr] = a0.w;
        As[lc+4][lr] = a1.x; As[lc+5][lr] = a1.y; As[lc+6][lr] = a1.z; As[lc+7][lr] = a1.w;
        Bs[lc+0][lr] = b0.x; Bs[lc+1][lr] = b0.y; Bs[lc+2][lr] = b0.z; Bs[lc+3][lr] = b0.w;
        Bs[lc+4][lr] = b1.x; Bs[lc+5][lr] = b1.y; Bs[lc+6][lr] = b1.z; Bs[lc+7][lr] = b1.w;
        __syncthreads();
        #pragma unroll
        for (int kk = 0; kk < BK; ++kk) {
            float a[8], b[8];
            *reinterpret_cast<float4*>(a)     = *reinterpret_cast<const float4*>(&As[kk][ty*8]);
            *reinterpret_cast<float4*>(a + 4) = *reinterpret_cast<const float4*>(&As[kk][ty*8 + 4]);
            *reinterpret_cast<float4*>(b)     = *reinterpret_cast<const float4*>(&Bs[kk][tx*8]);
            *reinterpret_cast<float4*>(b + 4) = *reinterpret_cast<const float4*>(&Bs[kk][tx*8 + 4]);
            #pragma unroll
            for (int i = 0; i < 8; ++i)
                #pragma unroll
                for (int j = 0; j < 8; ++j) acc[i][j] += a[i] * b[j];
        }
        __syncthreads();
    }

    float bb[8];
    *reinterpret_cast<float4*>(bb)     = *reinterpret_cast<const float4*>(bias + n0 + tx*8);
    *reinterpret_cast<float4*>(bb + 4) = *reinterpret_cast<const float4*>(bias + n0 + tx*8 + 4);
    #pragma unroll
    for (int i = 0; i < 8; ++i) {
        int m = m0 + ty*8 + i;
        float* cp = C + (size_t)m * KDIM + n0 + tx*8;
        *reinterpret_cast<float4*>(cp) =
            make_float4(acc[i][0]+bb[0], acc[i][1]+bb[1], acc[i][2]+bb[2], acc[i][3]+bb[3]);
        *reinterpret_cast<float4*>(cp + 4) =
            make_float4(acc[i][4]+bb[4], acc[i][5]+bb[5], acc[i][6]+bb[6], acc[i][7]+bb[7]);
    }
}

// ---------------- distance GEMM (bf16 HMMA) + candidate collection ----------
// Grid (MROWS/128, NSPLIT). Block: 128 rows x 1024 codes, 64-code tiles.
__global__ void __launch_bounds__(256) dist_cand_kernel() {
    constexpr int BM = 128, BN = 64, BK = 32, LDS = 40; // pad 8 elems -> conflict-free
    __shared__ __align__(16) __nv_bfloat16 As[2][BM * LDS];
    __shared__ __align__(16) __nv_bfloat16 Bs[2][BN * LDS];
    __shared__ unsigned s_best[BM];
    __shared__ int      s_cnt[BM];

    const int tid = threadIdx.x;
    const int lane = tid & 31, wid = tid >> 5;
    const int g = lane >> 2, tg = lane & 3;
    const int wm = (wid >> 1) * 32;   // 4 warps in m
    const int wn = (wid & 1) * 32;    // 2 warps in n
    const int m0 = blockIdx.x * BM;
    const int slice = blockIdx.y;
    const int n0 = slice * SLICE;

    if (tid < BM) { s_best[tid] = mono_f2u(-3.4e38f); s_cnt[tid] = 0; }

    const int ar0 = tid >> 2, ac = (tid & 3) << 3;
    const int br  = tid >> 2;
    uint32_t sA[2], sB[2];
    #pragma unroll
    for (int b = 0; b < 2; ++b) {
        sA[b] = (uint32_t)__cvta_generic_to_shared(&As[b][0]);
        sB[b] = (uint32_t)__cvta_generic_to_shared(&Bs[b][0]);
    }
    const int aRowA = wm + (lane & 15);
    const int aColA = ((lane >> 4) << 3);
    const int aRowB = wn + ((lane >> 4) << 3) + (lane & 7);
    const int aColB = (((lane >> 3) & 1) << 3);
    __syncthreads();

    for (int nt = 0; nt < SLICE / BN; ++nt) {
        float acc[2][4][4];
        #pragma unroll
        for (int i = 0; i < 2; ++i)
            #pragma unroll
            for (int j = 0; j < 4; ++j)
                #pragma unroll
                for (int q = 0; q < 4; ++q) acc[i][j][q] = 0.0f;

        {
            const int kt = 0;
            cpasync16(sA[0] + (uint32_t)(ar0 * LDS + ac) * 2,
                      g_zfb + (size_t)(m0 + ar0) * KDIM + kt * BK + ac);
            cpasync16(sA[0] + (uint32_t)((ar0 + 64) * LDS + ac) * 2,
                      g_zfb + (size_t)(m0 + ar0 + 64) * KDIM + kt * BK + ac);
            cpasync16(sB[0] + (uint32_t)(br * LDS + ac) * 2,
                      g_embnb + (size_t)(n0 + nt * BN + br) * KDIM + kt * BK + ac);
            cpasync_commit();
        }

        for (int kt = 0; kt < KDIM / BK; ++kt) {
            const int cur = kt & 1;
            if (kt < KDIM / BK - 1) {
                const int nx = 1 - cur, ktn = kt + 1;
                cpasync16(sA[nx] + (uint32_t)(ar0 * LDS + ac) * 2,
                          g_zfb + (size_t)(m0 + ar0) * KDIM + ktn * BK + ac);
                cpasync16(sA[nx] + (uint32_t)((ar0 + 64) * LDS + ac) * 2,
                          g_zfb + (size_t)(m0 + ar0 + 64) * KDIM + ktn * BK + ac);
                cpasync16(sB[nx] + (uint32_t)(br * LDS + ac) * 2,
                          g_embnb + (size_t)(n0 + nt * BN + br) * KDIM + ktn * BK + ac);
                cpasync_commit();
                cpasync_wait<1>();
            } else {
                cpasync_wait<0>();
            }
            __syncthreads();

            #pragma unroll
            for (int kk = 0; kk < BK; kk += 16) {
                unsigned a[2][4], b[4][2];
                #pragma unroll
                for (int ms = 0; ms < 2; ++ms) {
                    uint32_t addr = sA[cur] + (uint32_t)((aRowA + ms*16) * LDS + aColA + kk) * 2;
                    ldmatrix_x4(a[ms][0], a[ms][1], a[ms][2], a[ms][3], addr);
                }
                #pragma unroll
                for (int p = 0; p < 2; ++p) {
                    uint32_t addr = sB[cur] + (uint32_t)((aRowB + p*16) * LDS + aColB + kk) * 2;
                    ldmatrix_x4(b[2*p][0], b[2*p][1], b[2*p+1][0], b[2*p+1][1], addr);
                }
                #pragma unroll
                for (int ms = 0; ms < 2; ++ms)
                    #pragma unroll
                    for (int ns = 0; ns < 4; ++ns)
                        mma_bf16(acc[ms][ns], a[ms], b[ns]);
            }
            __syncthreads();
        }

        // ---- epilogue: running max + eps-filtered candidate append ----
        #pragma unroll
        for (int ms = 0; ms < 2; ++ms) {
            float mA = -3.4e38f, mB = -3.4e38f;
            #pragma unroll
            for (int ns = 0; ns < 4; ++ns) {
                mA = fmaxf(mA, fmaxf(acc[ms][ns][0], acc[ms][ns][1]));
                mB = fmaxf(mB, fmaxf(acc[ms][ns][2], acc[ms][ns][3]));
            }
            #pragma unroll
            for (int o = 1; o <= 2; o <<= 1) {
                mA = fmaxf(mA, __shfl_xor_sync(0xffffffffu, mA, o));
                mB = fmaxf(mB, __shfl_xor_sync(0xffffffffu, mB, o));
            }
            if (tg == 0) {
                atomicMax(&s_best[wm + ms*16 + g],     mono_f2u(mA));
                atomicMax(&s_best[wm + ms*16 + g + 8], mono_f2u(mB));
            }
        }
        __syncthreads();
        #pragma unroll
        for (int ms = 0; ms < 2; ++ms) {
            const int rA = wm + ms*16 + g, rB = rA + 8;
            const float thA = mono_u2f(s_best[rA]) - EPS;
            const float thB = mono_u2f(s_best[rB]) - EPS;
            #pragma unroll
            for (int ns = 0; ns < 4; ++ns) {
                const int code = n0 + nt * BN + wn + ns*8 + tg*2;
                #pragma unroll
                for (int h = 0; h < 2; ++h) {
                    float vA = acc[ms][ns][h];
                    if (vA > thA) {
                        int pos = atomicAdd(&s_cnt[rA], 1);
                        if (pos < CAP_S)
                            g_cand[(size_t)(m0 + rA) * CAND_STRIDE + slice * CAP_S + pos] =
                                make_int2(code + h, __float_as_int(vA));
                    }
                    float vB = acc[ms][ns][2 + h];
                    if (vB > thB) {
                        int pos = atomicAdd(&s_cnt[rB], 1);
                        if (pos < CAP_S)
                            g_cand[(size_t)(m0 + rB) * CAND_STRIDE + slice * CAP_S + pos] =
                                make_int2(code + h, __float_as_int(vB));
                    }
                }
            }
        }
    }
    __syncthreads();
    if (tid < BM) g_ccnt[(m0 + tid) * NSPLIT + slice] = s_cnt[tid];
}

// ---------------- exact fp32 rescore of candidates -> argmax index ----------
__global__ void __launch_bounds__(256) rescore_kernel() {
    const int wid = threadIdx.x >> 5;
    const int lane = threadIdx.x & 31;
    const int row = blockIdx.x * 8 + wid;
    const float* zr = g_zf + (size_t)row * KDIM;
    float zv[16];
    #pragma unroll
    for (int i = 0; i < 16; ++i) zv[i] = zr[lane + 32*i];

    int cnt_l = (lane < NSPLIT) ? g_ccnt[row * NSPLIT + lane] : 0;
    unsigned ovf_mask = __ballot_sync(0xffffffffu, (lane < NSPLIT) && (cnt_l > CAP_S)) & 0xFFu;

    float best = -3.4e38f;
    int bi = NEMB;
    const int2* cr = g_cand + (size_t)row * CAND_STRIDE;

    // pass 1: global bf16-score max over candidates of non-overflowed slices
    float ms = -3.4e38f;
    for (int s = 0; s < NSPLIT; ++s) {
        if (ovf_mask & (1u << s)) continue;
        int c = __shfl_sync(0xffffffffu, cnt_l, s);
        for (int j = lane; j < c; j += 32)
            ms = fmaxf(ms, __int_as_float(cr[s * CAP_S + j].y));
    }
    #pragma unroll
    for (int o = 16; o > 0; o >>= 1) ms = fmaxf(ms, __shfl_xor_sync(0xffffffffu, ms, o));
    const float th = ms - EPS;

    // pass 2: exact fp32 dot for above-threshold candidates (non-ovf slices)
    for (int s = 0; s < NSPLIT; ++s) {
        if (ovf_mask & (1u << s)) continue;
        int c = __shfl_sync(0xffffffffu, cnt_l, s);
        for (int j = 0; j < c; ++j) {
            int2 e = cr[s * CAP_S + j];            // broadcast load
            if (__int_as_float(e.y) <= th) continue;
            const float* er = g_embn + (size_t)e.x * KDIM;
            float sum = 0.0f;
            #pragma unroll
            for (int i = 0; i < 16; ++i) sum += zv[i] * er[lane + 32*i];
            #pragma unroll
            for (int o = 16; o > 0; o >>= 1) sum += __shfl_xor_sync(0xffffffffu, sum, o);
            if (sum > best || (sum == best && e.x < bi)) { best = sum; bi = e.x; }
        }
    }

    // pass 3: overflowed slices -> exact fp32 scan of that 1024-code slice only
    for (int s = 0; s < NSPLIT; ++s) {
        if (!(ovf_mask & (1u << s))) continue;
        for (int code = s * SLICE; code < (s + 1) * SLICE; ++code) {
            const float* er = g_embn + (size_t)code * KDIM;
            float sum = 0.0f;
            #pragma unroll
            for (int i = 0; i < 16; ++i) sum += zv[i] * er[lane + 32*i];
            #pragma unroll
            for (int o = 16; o > 0; o >>= 1) sum += __shfl_xor_sync(0xffffffffu, sum, o);
            if (sum > best || (sum == best && code < bi)) { best = sum; bi = code; }
        }
    }
    if (lane == 0) g_idx[row] = bi;
}

// ---------------- write idx (cast to float) to output tail ------------------
__global__ void write_idx_kernel(float* __restrict__ dst, int n) {
    int i = blockIdx.x * blockDim.x + threadIdx.x;
    if (i < n) dst[i] = (float)g_idx[i];
}

// ---------------- launch ----------------------------------------------------
extern "C" void kernel_launch(void* const* d_in, const int* in_sizes, int n_in,
                              void* d_out, int out_size) {
    const float* z     = (const float*)d_in[0];
    // d_in[1] = mask (all true; unused by the reference math)
    const float* W_in  = (const float*)d_in[2];
    const float* b_in  = (const float*)d_in[3];
    const float* W_out = (const float*)d_in[4];
    const float* b_out = (const float*)d_in[5];
    const float* emb   = (const float*)d_in[6];
    float* out = (float*)d_out;

    norm_emb_kernel<<<NEMB, 128>>>(emb);
    sgemm512<false><<<dim3(KDIM/128, MROWS/128), 256>>>(z, W_in, b_in, nullptr);
    norm_zf_kernel<<<MROWS, 128>>>();
    dist_cand_kernel<<<dim3(MROWS/128, NSPLIT), 256>>>();
    rescore_kernel<<<MROWS/8, 256>>>();
    sgemm512<true><<<dim3(KDIM/128, MROWS/128), 256>>>(nullptr, W_out, b_out, out);
    int tail = out_size - MROWS * KDIM;
    if (tail > 0) {
        int n = tail < MROWS ? tail : MROWS;
        write_idx_kernel<<<(n + 255) / 256, 256>>>(out + (size_t)MROWS * KDIM, n);
    }
}

// round 12
// speedup vs baseline: 5.9971x; 1.0829x over previous
#include <cuda_runtime.h>
#include <cuda_bf16.h>
#include <stdint.h>

// Problem constants: B=8, S=2048 -> M=16384 rows; LATENT = EDIM = 512; NE = 8192.
#define MROWS 16384
#define KDIM  512
#define NEMB  8192
#define NSPLIT 8
#define SLICE (NEMB / NSPLIT)      // 1024 codes per block-column
#define CAP_S 48                   // candidate slots per (row, slice); mean ~10
#define CAND_STRIDE (NSPLIT * CAP_S)
#define EPS 4e-3f

// ---------------- scratch (static __device__ arrays; no allocs) -------------
__device__ float                        g_zf[(size_t)MROWS * KDIM];
__device__ __align__(16) __nv_bfloat16  g_zfb[(size_t)MROWS * KDIM];
__device__ float                        g_embn[(size_t)NEMB * KDIM];
__device__ __align__(16) __nv_bfloat16  g_embnb[(size_t)NEMB * KDIM];
__device__ int2                         g_cand[(size_t)MROWS * CAND_STRIDE]; // {code, score bits}
__device__ int                          g_ccnt[MROWS * NSPLIT];
__device__ int                          g_idx[MROWS];

// ---------------- helpers ---------------------------------------------------
__device__ __forceinline__ unsigned mono_f2u(float f) {
    int b = __float_as_int(f);
    return (b >= 0) ? ((unsigned)b | 0x80000000u) : ~(unsigned)b;
}
__device__ __forceinline__ float mono_u2f(unsigned u) {
    return (u & 0x80000000u) ? __int_as_float((int)(u ^ 0x80000000u))
                             : __int_as_float((int)~u);
}
__device__ __forceinline__ void cpasync16(uint32_t dst, const void* src) {
    asm volatile("cp.async.cg.shared.global [%0], [%1], 16;\n" :: "r"(dst), "l"(src));
}
__device__ __forceinline__ void cpasync_commit() {
    asm volatile("cp.async.commit_group;\n");
}
template<int N>
__device__ __forceinline__ void cpasync_wait() {
    asm volatile("cp.async.wait_group %0;\n" :: "n"(N));
}
__device__ __forceinline__ void ldmatrix_x4(unsigned& r0, unsigned& r1, unsigned& r2,
                                            unsigned& r3, uint32_t addr) {
    asm volatile("ldmatrix.sync.aligned.m8n8.x4.shared.b16 {%0,%1,%2,%3}, [%4];\n"
                 : "=r"(r0), "=r"(r1), "=r"(r2), "=r"(r3) : "r"(addr));
}
__device__ __forceinline__ void mma_bf16(float* c, const unsigned* a, const unsigned* b) {
    asm volatile(
        "mma.sync.aligned.m16n8k16.row.col.f32.bf16.bf16.f32 "
        "{%0,%1,%2,%3}, {%4,%5,%6,%7}, {%8,%9}, {%0,%1,%2,%3};\n"
        : "+f"(c[0]), "+f"(c[1]), "+f"(c[2]), "+f"(c[3])
        : "r"(a[0]), "r"(a[1]), "r"(a[2]), "r"(a[3]), "r"(b[0]), "r"(b[1]));
}

// ---------------- row L2 normalize: emb -> g_embn / g_embnb -----------------
__global__ void norm_emb_kernel(const float* __restrict__ emb) {
    int row = blockIdx.x;
    int t = threadIdx.x;   // 128 threads, 512 floats per row
    float4 v = reinterpret_cast<const float4*>(emb + (size_t)row * KDIM)[t];
    float ss = v.x*v.x + v.y*v.y + v.z*v.z + v.w*v.w;
    #pragma unroll
    for (int o = 16; o > 0; o >>= 1) ss += __shfl_xor_sync(0xffffffffu, ss, o);
    __shared__ float ws[4];
    if ((t & 31) == 0) ws[t >> 5] = ss;
    __syncthreads();
    float s = 1.0f / fmaxf(sqrtf(ws[0] + ws[1] + ws[2] + ws[3]), 1e-12f);
    float4 o4 = make_float4(v.x*s, v.y*s, v.z*s, v.w*s);
    reinterpret_cast<float4*>(g_embn + (size_t)row * KDIM)[t] = o4;
    __nv_bfloat162* ob = reinterpret_cast<__nv_bfloat162*>(g_embnb + (size_t)row * KDIM);
    ob[t*2]     = __floats2bfloat162_rn(o4.x, o4.y);
    ob[t*2 + 1] = __floats2bfloat162_rn(o4.z, o4.w);
}

// ---------------- row L2 normalize: g_zf (in place) -> g_zfb ----------------
__global__ void norm_zf_kernel() {
    int row = blockIdx.x;
    int t = threadIdx.x;
    float4 v = reinterpret_cast<const float4*>(g_zf + (size_t)row * KDIM)[t];
    float ss = v.x*v.x + v.y*v.y + v.z*v.z + v.w*v.w;
    #pragma unroll
    for (int o = 16; o > 0; o >>= 1) ss += __shfl_xor_sync(0xffffffffu, ss, o);
    __shared__ float ws[4];
    if ((t & 31) == 0) ws[t >> 5] = ss;
    __syncthreads();
    float s = 1.0f / fmaxf(sqrtf(ws[0] + ws[1] + ws[2] + ws[3]), 1e-12f);
    float4 o4 = make_float4(v.x*s, v.y*s, v.z*s, v.w*s);
    reinterpret_cast<float4*>(g_zf + (size_t)row * KDIM)[t] = o4;
    __nv_bfloat162* ob = reinterpret_cast<__nv_bfloat162*>(g_zfb + (size_t)row * KDIM);
    ob[t*2]     = __floats2bfloat162_rn(o4.x, o4.y);
    ob[t*2 + 1] = __floats2bfloat162_rn(o4.z, o4.w);
}

// ---------------- fp32 SGEMM: C[m][n] = sum_k A[m][k]*B[n][k] + bias[n] -----
template<bool GATHER>
__global__ void __launch_bounds__(256) sgemm512(const float* __restrict__ Aext,
                                                const float* __restrict__ Bw,
                                                const float* __restrict__ bias,
                                                float* __restrict__ Cext) {
    constexpr int BM = 128, BN = 128, BK = 16;
    __shared__ float As[BK][BM];
    __shared__ float Bs[BK][BN];
    const int tid = threadIdx.x;
    const int tx = tid & 15, ty = tid >> 4;
    const int m0 = blockIdx.y * BM, n0 = blockIdx.x * BN;
    const int lr = tid >> 1;
    const int lc = (tid & 1) << 3;
    const float* Arow;
    if (GATHER) Arow = g_embn + (size_t)g_idx[m0 + lr] * KDIM;
    else        Arow = Aext + (size_t)(m0 + lr) * KDIM;
    const float* Brow = Bw + (size_t)(n0 + lr) * KDIM;
    float* C = GATHER ? Cext : g_zf;

    float acc[8][8];
    #pragma unroll
    for (int i = 0; i < 8; ++i)
        #pragma unroll
        for (int j = 0; j < 8; ++j) acc[i][j] = 0.0f;

    for (int k0 = 0; k0 < KDIM; k0 += BK) {
        float4 a0 = *reinterpret_cast<const float4*>(Arow + k0 + lc);
        float4 a1 = *reinterpret_cast<const float4*>(Arow + k0 + lc + 4);
        float4 b0 = *reinterpret_cast<const float4*>(Brow + k0 + lc);
        float4 b1 = *reinterpret_cast<const float4*>(Brow + k0 + lc + 4);
        As[lc+0][lr] = a0.x; As[lc+1][lr] = a0.y; As[lc+2][lr] = a0.z; As[lc+3][lr] = a0.w;
        As[lc+4][lr] = a1.x; As[lc+5][lr] = a1.y; As[lc+6][lr] = a1.z; As[lc+7][lr] = a1.w;
        Bs[lc+0][lr] = b0.x; Bs[lc+1][lr] = b0.y; Bs[lc+2][lr] = b0.z; Bs[lc+3][lr] = b0.w;
        Bs[lc+4][lr] = b1.x; Bs[lc+5][lr] = b1.y; Bs[lc+6][lr] = b1.z; Bs[lc+7][lr] = b1.w;
        __syncthreads();
        #pragma unroll
        for (int kk = 0; kk < BK; ++kk) {
            float a[8], b[8];
            *reinterpret_cast<float4*>(a)     = *reinterpret_cast<const float4*>(&As[kk][ty*8]);
            *reinterpret_cast<float4*>(a + 4) = *reinterpret_cast<const float4*>(&As[kk][ty*8 + 4]);
            *reinterpret_cast<float4*>(b)     = *reinterpret_cast<const float4*>(&Bs[kk][tx*8]);
            *reinterpret_cast<float4*>(b + 4) = *reinterpret_cast<const float4*>(&Bs[kk][tx*8 + 4]);
            #pragma unroll
            for (int i = 0; i < 8; ++i)
                #pragma unroll
                for (int j = 0; j < 8; ++j) acc[i][j] += a[i] * b[j];
        }
        __syncthreads();
    }

    float bb[8];
    *reinterpret_cast<float4*>(bb)     = *reinterpret_cast<const float4*>(bias + n0 + tx*8);
    *reinterpret_cast<float4*>(bb + 4) = *reinterpret_cast<const float4*>(bias + n0 + tx*8 + 4);
    #pragma unroll
    for (int i = 0; i < 8; ++i) {
        int m = m0 + ty*8 + i;
        float* cp = C + (size_t)m * KDIM + n0 + tx*8;
        *reinterpret_cast<float4*>(cp) =
            make_float4(acc[i][0]+bb[0], acc[i][1]+bb[1], acc[i][2]+bb[2], acc[i][3]+bb[3]);
        *reinterpret_cast<float4*>(cp + 4) =
            make_float4(acc[i][4]+bb[4], acc[i][5]+bb[5], acc[i][6]+bb[6], acc[i][7]+bb[7]);
    }
}

// ---------------- distance GEMM (bf16 HMMA) + candidate collection ----------
// Grid (MROWS/128, NSPLIT), 512 threads. Block: 128 rows x 1024 codes in
// 128-code tiles; 16 warps (4m x 4n), warp tile 32x32 == R6-measured 74-reg
// per-thread structure (acc[2][4][4], same ldmatrix/mma counts).
__global__ void __launch_bounds__(512) dist_cand_kernel() {
    constexpr int BM = 128, BN = 128, BK = 32, LDS = 40;
    __shared__ __align__(16) __nv_bfloat16 As[2][BM * LDS];
    __shared__ __align__(16) __nv_bfloat16 Bs[2][BN * LDS];
    __shared__ unsigned s_best[BM];
    __shared__ int      s_cnt[BM];

    const int tid = threadIdx.x;
    const int lane = tid & 31, wid = tid >> 5;
    const int g = lane >> 2, tg = lane & 3;
    const int wm = (wid & 3) * 32;    // 4 warps in m
    const int wn = (wid >> 2) * 32;   // 4 warps in n
    const int m0 = blockIdx.x * BM;
    const int slice = blockIdx.y;
    const int n0 = slice * SLICE;

    if (tid < BM) { s_best[tid] = mono_f2u(-3.4e38f); s_cnt[tid] = 0; }

    // loader: 128x32 tile = 512 16B chunks; thread t loads one A + one B chunk
    const int r0 = tid >> 2, cblk = (tid & 3) << 3;
    uint32_t sA[2], sB[2];
    #pragma unroll
    for (int b = 0; b < 2; ++b) {
        sA[b] = (uint32_t)__cvta_generic_to_shared(&As[b][0]);
        sB[b] = (uint32_t)__cvta_generic_to_shared(&Bs[b][0]);
    }
    const uint32_t dOff = (uint32_t)(r0 * LDS + cblk) * 2;
    const size_t arow = (size_t)(m0 + r0) * KDIM;

    const int aRowA = wm + (lane & 15);
    const int aColA = ((lane >> 4) << 3);
    const int aRowB = wn + ((lane >> 4) << 3) + (lane & 7);
    const int aColB = (((lane >> 3) & 1) << 3);
    __syncthreads();

    for (int nt = 0; nt < SLICE / BN; ++nt) {
        const size_t brow = (size_t)(n0 + nt * BN + r0) * KDIM;
        float acc[2][4][4];
        #pragma unroll
        for (int i = 0; i < 2; ++i)
            #pragma unroll
            for (int j = 0; j < 4; ++j)
                #pragma unroll
                for (int q = 0; q < 4; ++q) acc[i][j][q] = 0.0f;

        {   // prologue: k-tile 0 -> buffer 0
            cpasync16(sA[0] + dOff, g_zfb + arow + cblk);
            cpasync16(sB[0] + dOff, g_embnb + brow + cblk);
            cpasync_commit();
        }

        for (int kt = 0; kt < KDIM / BK; ++kt) {
            const int buf = kt & 1;
            if (kt < KDIM / BK - 1) {
                const int nb = 1 - buf, k0 = (kt + 1) * BK;
                cpasync16(sA[nb] + dOff, g_zfb + arow + k0 + cblk);
                cpasync16(sB[nb] + dOff, g_embnb + brow + k0 + cblk);
                cpasync_commit();
                cpasync_wait<1>();
            } else {
                cpasync_wait<0>();
            }
            __syncthreads();
            #pragma unroll
            for (int kk = 0; kk < BK; kk += 16) {
                unsigned a[2][4], b[4][2];
                #pragma unroll
                for (int ms = 0; ms < 2; ++ms) {
                    uint32_t addr = sA[buf] + (uint32_t)((aRowA + ms*16) * LDS + aColA + kk) * 2;
                    ldmatrix_x4(a[ms][0], a[ms][1], a[ms][2], a[ms][3], addr);
                }
                #pragma unroll
                for (int p = 0; p < 2; ++p) {
                    uint32_t addr = sB[buf] + (uint32_t)((aRowB + p*16) * LDS + aColB + kk) * 2;
                    ldmatrix_x4(b[2*p][0], b[2*p][1], b[2*p+1][0], b[2*p+1][1], addr);
                }
                #pragma unroll
                for (int ms = 0; ms < 2; ++ms)
                    #pragma unroll
                    for (int ns = 0; ns < 4; ++ns)
                        mma_bf16(acc[ms][ns], a[ms], b[ns]);
            }
            __syncthreads();
        }

        // ---- epilogue: running max + eps-filtered candidate append ----
        #pragma unroll
        for (int ms = 0; ms < 2; ++ms) {
            float mA = -3.4e38f, mB = -3.4e38f;
            #pragma unroll
            for (int ns = 0; ns < 4; ++ns) {
                mA = fmaxf(mA, fmaxf(acc[ms][ns][0], acc[ms][ns][1]));
                mB = fmaxf(mB, fmaxf(acc[ms][ns][2], acc[ms][ns][3]));
            }
            #pragma unroll
            for (int o = 1; o <= 2; o <<= 1) {
                mA = fmaxf(mA, __shfl_xor_sync(0xffffffffu, mA, o));
                mB = fmaxf(mB, __shfl_xor_sync(0xffffffffu, mB, o));
            }
            if (tg == 0) {
                atomicMax(&s_best[wm + ms*16 + g],     mono_f2u(mA));
                atomicMax(&s_best[wm + ms*16 + g + 8], mono_f2u(mB));
            }
        }
        __syncthreads();
        #pragma unroll
        for (int ms = 0; ms < 2; ++ms) {
            const int rA = wm + ms*16 + g, rB = rA + 8;
            const float thA = mono_u2f(s_best[rA]) - EPS;
            const float thB = mono_u2f(s_best[rB]) - EPS;
            #pragma unroll
            for (int ns = 0; ns < 4; ++ns) {
                const int code = n0 + nt * BN + wn + ns*8 + tg*2;
                #pragma unroll
                for (int h = 0; h < 2; ++h) {
                    float vA = acc[ms][ns][h];
                    if (vA > thA) {
                        int pos = atomicAdd(&s_cnt[rA], 1);
                        if (pos < CAP_S)
                            g_cand[(size_t)(m0 + rA) * CAND_STRIDE + slice * CAP_S + pos] =
                                make_int2(code + h, __float_as_int(vA));
                    }
                    float vB = acc[ms][ns][2 + h];
                    if (vB > thB) {
                        int pos = atomicAdd(&s_cnt[rB], 1);
                        if (pos < CAP_S)
                            g_cand[(size_t)(m0 + rB) * CAND_STRIDE + slice * CAP_S + pos] =
                                make_int2(code + h, __float_as_int(vB));
                    }
                }
            }
        }
        // racing atomicMax from faster warps only raises thresholds (safe:
        // candidate set stays a superset of the argmax); no extra barrier.
    }
    __syncthreads();
    if (tid < BM) g_ccnt[(m0 + tid) * NSPLIT + slice] = s_cnt[tid];
}

// ---------------- exact fp32 rescore of candidates -> argmax index ----------
__global__ void __launch_bounds__(256) rescore_kernel() {
    const int wid = threadIdx.x >> 5;
    const int lane = threadIdx.x & 31;
    const int row = blockIdx.x * 8 + wid;
    const float* zr = g_zf + (size_t)row * KDIM;
    float zv[16];
    #pragma unroll
    for (int i = 0; i < 16; ++i) zv[i] = zr[lane + 32*i];

    int cnt_l = (lane < NSPLIT) ? g_ccnt[row * NSPLIT + lane] : 0;
    unsigned ovf_mask = __ballot_sync(0xffffffffu, (lane < NSPLIT) && (cnt_l > CAP_S)) & 0xFFu;

    float best = -3.4e38f;
    int bi = NEMB;
    const int2* cr = g_cand + (size_t)row * CAND_STRIDE;

    // pass 1: global bf16-score max over candidates of non-overflowed slices
    float ms = -3.4e38f;
    for (int s = 0; s < NSPLIT; ++s) {
        if (ovf_mask & (1u << s)) continue;
        int c = __shfl_sync(0xffffffffu, cnt_l, s);
        for (int j = lane; j < c; j += 32)
            ms = fmaxf(ms, __int_as_float(cr[s * CAP_S + j].y));
    }
    #pragma unroll
    for (int o = 16; o > 0; o >>= 1) ms = fmaxf(ms, __shfl_xor_sync(0xffffffffu, ms, o));
    const float th = ms - EPS;

    // pass 2: exact fp32 dot for above-threshold candidates (non-ovf slices)
    for (int s = 0; s < NSPLIT; ++s) {
        if (ovf_mask & (1u << s)) continue;
        int c = __shfl_sync(0xffffffffu, cnt_l, s);
        for (int j = 0; j < c; ++j) {
            int2 e = cr[s * CAP_S + j];            // broadcast load
            if (__int_as_float(e.y) <= th) continue;
            const float* er = g_embn + (size_t)e.x * KDIM;
            float sum = 0.0f;
            #pragma unroll
            for (int i = 0; i < 16; ++i) sum += zv[i] * er[lane + 32*i];
            #pragma unroll
            for (int o = 16; o > 0; o >>= 1) sum += __shfl_xor_sync(0xffffffffu, sum, o);
            if (sum > best || (sum == best && e.x < bi)) { best = sum; bi = e.x; }
        }
    }

    // pass 3: overflowed slices -> exact fp32 scan of that 1024-code slice only
    for (int s = 0; s < NSPLIT; ++s) {
        if (!(ovf_mask & (1u << s))) continue;
        for (int code = s * SLICE; code < (s + 1) * SLICE; ++code) {
            const float* er = g_embn + (size_t)code * KDIM;
            float sum = 0.0f;
            #pragma unroll
            for (int i = 0; i < 16; ++i) sum += zv[i] * er[lane + 32*i];
            #pragma unroll
            for (int o = 16; o > 0; o >>= 1) sum += __shfl_xor_sync(0xffffffffu, sum, o);
            if (sum > best || (sum == best && code < bi)) { best = sum; bi = code; }
        }
    }
    if (lane == 0) g_idx[row] = bi;
}

// ---------------- write idx (cast to float) to output tail ------------------
__global__ void write_idx_kernel(float* __restrict__ dst, int n) {
    int i = blockIdx.x * blockDim.x + threadIdx.x;
    if (i < n) dst[i] = (float)g_idx[i];
}

// ---------------- launch ----------------------------------------------------
extern "C" void kernel_launch(void* const* d_in, const int* in_sizes, int n_in,
                              void* d_out, int out_size) {
    const float* z     = (const float*)d_in[0];
    // d_in[1] = mask (all true; unused by the reference math)
    const float* W_in  = (const float*)d_in[2];
    const float* b_in  = (const float*)d_in[3];
    const float* W_out = (const float*)d_in[4];
    const float* b_out = (const float*)d_in[5];
    const float* emb   = (const float*)d_in[6];
    float* out = (float*)d_out;

    norm_emb_kernel<<<NEMB, 128>>>(emb);
    sgemm512<false><<<dim3(KDIM/128, MROWS/128), 256>>>(z, W_in, b_in, nullptr);
    norm_zf_kernel<<<MROWS, 128>>>();
    dist_cand_kernel<<<dim3(MROWS/128, NSPLIT), 512>>>();
    rescore_kernel<<<MROWS/8, 256>>>();
    sgemm512<true><<<dim3(KDIM/128, MROWS/128), 256>>>(nullptr, W_out, b_out, out);
    int tail = out_size - MROWS * KDIM;
    if (tail > 0) {
        int n = tail < MROWS ? tail : MROWS;
        write_idx_kernel<<<(n + 255) / 256, 256>>>(out + (size_t)MROWS * KDIM, n);
    }
}

// round 17
// speedup vs baseline: 7.8625x; 1.3111x over previous
#include <cuda_runtime.h>
#include <cuda_bf16.h>
#include <stdint.h>

// Problem constants: B=8, S=2048 -> M=16384 rows; LATENT = EDIM = 512; NE = 8192.
#define MROWS 16384
#define KDIM  512
#define NEMB  8192
#define NSPLIT 8
#define SLICE (NEMB / NSPLIT)      // 1024 codes per block-column
#define CAP_S 48                   // candidate slots per (row, slice); mean ~10
#define CAND_STRIDE (NSPLIT * CAP_S)
#define EPS 4e-3f

#define ZSZ ((size_t)MROWS * KDIM)   // elements in one z half
#define WSZ ((size_t)KDIM * KDIM)    // elements in one weight half
#define ESZ ((size_t)NEMB * KDIM)    // elements in one emb half

// ---------------- scratch (static __device__ arrays; no allocs) -------------
__device__ float                        g_zf[(size_t)MROWS * KDIM];
__device__ __align__(16) __nv_bfloat16  g_zfb[(size_t)MROWS * KDIM];
__device__ float                        g_embn[(size_t)NEMB * KDIM];
__device__ __align__(16) __nv_bfloat16  g_embnb[(size_t)NEMB * KDIM];
__device__ __align__(16) __nv_bfloat16  g_zs[2 * ZSZ];     // z hi || z lo
__device__ __align__(16) __nv_bfloat16  g_wins[2 * WSZ];   // W_in hi || lo
__device__ __align__(16) __nv_bfloat16  g_wouts[2 * WSZ];  // W_out hi || lo
__device__ __align__(16) __nv_bfloat16  g_embs[2 * ESZ];   // embn hi || lo
__device__ int2                         g_cand[(size_t)MROWS * CAND_STRIDE]; // {code, score bits}
__device__ int                          g_ccnt[MROWS * NSPLIT];
__device__ int                          g_idx[MROWS];

// ---------------- helpers ---------------------------------------------------
__device__ __forceinline__ unsigned mono_f2u(float f) {
    int b = __float_as_int(f);
    return (b >= 0) ? ((unsigned)b | 0x80000000u) : ~(unsigned)b;
}
__device__ __forceinline__ float mono_u2f(unsigned u) {
    return (u & 0x80000000u) ? __int_as_float((int)(u ^ 0x80000000u))
                             : __int_as_float((int)~u);
}
__device__ __forceinline__ void cpasync16(uint32_t dst, const void* src) {
    asm volatile("cp.async.cg.shared.global [%0], [%1], 16;\n" :: "r"(dst), "l"(src));
}
__device__ __forceinline__ void cpasync_commit() {
    asm volatile("cp.async.commit_group;\n");
}
template<int N>
__device__ __forceinline__ void cpasync_wait() {
    asm volatile("cp.async.wait_group %0;\n" :: "n"(N));
}
__device__ __forceinline__ void ldmatrix_x4(unsigned& r0, unsigned& r1, unsigned& r2,
                                            unsigned& r3, uint32_t addr) {
    asm volatile("ldmatrix.sync.aligned.m8n8.x4.shared.b16 {%0,%1,%2,%3}, [%4];\n"
                 : "=r"(r0), "=r"(r1), "=r"(r2), "=r"(r3) : "r"(addr));
}
__device__ __forceinline__ void mma_bf16(float* c, const unsigned* a, const unsigned* b) {
    asm volatile(
        "mma.sync.aligned.m16n8k16.row.col.f32.bf16.bf16.f32 "
        "{%0,%1,%2,%3}, {%4,%5,%6,%7}, {%8,%9}, {%0,%1,%2,%3};\n"
        : "+f"(c[0]), "+f"(c[1]), "+f"(c[2]), "+f"(c[3])
        : "r"(a[0]), "r"(a[1]), "r"(a[2]), "r"(a[3]), "r"(b[0]), "r"(b[1]));
}

// ---------------- row L2 normalize + split: emb -> g_embn/g_embnb/g_embs ----
// All device-symbol writes happen INSIDE device code (no symbols as kernel args).
__global__ void norm_emb_kernel(const float* __restrict__ emb) {
    int row = blockIdx.x;
    int t = threadIdx.x;   // 128 threads, 512 floats per row
    float4 v = reinterpret_cast<const float4*>(emb + (size_t)row * KDIM)[t];
    float ss = v.x*v.x + v.y*v.y + v.z*v.z + v.w*v.w;
    #pragma unroll
    for (int o = 16; o > 0; o >>= 1) ss += __shfl_xor_sync(0xffffffffu, ss, o);
    __shared__ float ws[4];
    if ((t & 31) == 0) ws[t >> 5] = ss;
    __syncthreads();
    float s = 1.0f / fmaxf(sqrtf(ws[0] + ws[1] + ws[2] + ws[3]), 1e-12f);
    float o0 = v.x*s, o1 = v.y*s, o2 = v.z*s, o3 = v.w*s;
    reinterpret_cast<float4*>(g_embn + (size_t)row * KDIM)[t] = make_float4(o0, o1, o2, o3);
    __nv_bfloat16 h0 = __float2bfloat16(o0);
    __nv_bfloat16 h1 = __float2bfloat16(o1);
    __nv_bfloat16 h2 = __float2bfloat16(o2);
    __nv_bfloat16 h3 = __float2bfloat16(o3);
    __nv_bfloat16 l0 = __float2bfloat16(o0 - __bfloat162float(h0));
    __nv_bfloat16 l1 = __float2bfloat16(o1 - __bfloat162float(h1));
    __nv_bfloat16 l2 = __float2bfloat16(o2 - __bfloat162float(h2));
    __nv_bfloat16 l3 = __float2bfloat16(o3 - __bfloat162float(h3));
    __nv_bfloat162* ob = reinterpret_cast<__nv_bfloat162*>(g_embnb + (size_t)row * KDIM);
    __nv_bfloat162* oh = reinterpret_cast<__nv_bfloat162*>(g_embs + (size_t)row * KDIM);
    __nv_bfloat162* ol = reinterpret_cast<__nv_bfloat162*>(g_embs + ESZ + (size_t)row * KDIM);
    ob[t*2]     = __nv_bfloat162(h0, h1);
    ob[t*2 + 1] = __nv_bfloat162(h2, h3);
    oh[t*2]     = __nv_bfloat162(h0, h1);
    oh[t*2 + 1] = __nv_bfloat162(h2, h3);
    ol[t*2]     = __nv_bfloat162(l0, l1);
    ol[t*2 + 1] = __nv_bfloat162(l2, l3);
}

// ---------------- row L2 normalize: g_zf (in place) -> g_zfb ----------------
__global__ void norm_zf_kernel() {
    int row = blockIdx.x;
    int t = threadIdx.x;
    float4 v = reinterpret_cast<const float4*>(g_zf + (size_t)row * KDIM)[t];
    float ss = v.x*v.x + v.y*v.y + v.z*v.z + v.w*v.w;
    #pragma unroll
    for (int o = 16; o > 0; o >>= 1) ss += __shfl_xor_sync(0xffffffffu, ss, o);
    __shared__ float ws[4];
    if ((t & 31) == 0) ws[t >> 5] = ss;
    __syncthreads();
    float s = 1.0f / fmaxf(sqrtf(ws[0] + ws[1] + ws[2] + ws[3]), 1e-12f);
    float4 o4 = make_float4(v.x*s, v.y*s, v.z*s, v.w*s);
    reinterpret_cast<float4*>(g_zf + (size_t)row * KDIM)[t] = o4;
    __nv_bfloat162* ob = reinterpret_cast<__nv_bfloat162*>(g_zfb + (size_t)row * KDIM);
    ob[t*2]     = __floats2bfloat162_rn(o4.x, o4.y);
    ob[t*2 + 1] = __floats2bfloat162_rn(o4.z, o4.w);
}

// ---------------- fp32 -> (hi || lo) splits into fixed global symbols -------
// Input x is a HARNESS pointer (legal kernel arg); outputs are device symbols
// referenced inside device code only.
#define MAKE_SPLIT(NAME, HSYM, HALF, N4) \
__global__ void NAME(const float* __restrict__ x) { \
    int i = blockIdx.x * blockDim.x + threadIdx.x; \
    if (i >= (N4)) return; \
    float4 v = reinterpret_cast<const float4*>(x)[i]; \
    __nv_bfloat16 h0 = __float2bfloat16(v.x); \
    __nv_bfloat16 h1 = __float2bfloat16(v.y); \
    __nv_bfloat16 h2 = __float2bfloat16(v.z); \
    __nv_bfloat16 h3 = __float2bfloat16(v.w); \
    __nv_bfloat16 l0 = __float2bfloat16(v.x - __bfloat162float(h0)); \
    __nv_bfloat16 l1 = __float2bfloat16(v.y - __bfloat162float(h1)); \
    __nv_bfloat16 l2 = __float2bfloat16(v.z - __bfloat162float(h2)); \
    __nv_bfloat16 l3 = __float2bfloat16(v.w - __bfloat162float(h3)); \
    __nv_bfloat162* oh = reinterpret_cast<__nv_bfloat162*>(HSYM); \
    __nv_bfloat162* ol = reinterpret_cast<__nv_bfloat162*>((HSYM) + (HALF)); \
    oh[i*2]     = __nv_bfloat162(h0, h1); \
    oh[i*2 + 1] = __nv_bfloat162(h2, h3); \
    ol[i*2]     = __nv_bfloat162(l0, l1); \
    ol[i*2 + 1] = __nv_bfloat162(l2, l3); \
}
MAKE_SPLIT(split_z_kernel,    g_zs,    ZSZ, (int)(ZSZ / 4))
MAKE_SPLIT(split_win_kernel,  g_wins,  WSZ, (int)(WSZ / 4))
MAKE_SPLIT(split_wout_kernel, g_wouts, WSZ, (int)(WSZ / 4))

// ---------------- split-bf16 tensor GEMM (single fused 48-iter loop) --------
// K=1536 schedule over one loop: kt 0-15 Ah*Bh, 16-31 Ah*Bl, 32-47 Al*Bh.
// Segment selection = branchless size_t offsets into single global symbols
// (no pointer selection). Loop body byte-identical to the proven dist kernel.
#define HGEMM_KERNEL_BODY(ASYM, AHALF, BSYM, BHALF, AROW_EXPR, CDST) \
    constexpr int LDS = 40; \
    __shared__ __align__(16) __nv_bfloat16 As[2][128 * LDS]; \
    __shared__ __align__(16) __nv_bfloat16 Bs[2][128 * LDS]; \
    const int tid = threadIdx.x; \
    const int lane = tid & 31, wid = tid >> 5; \
    const int g = lane >> 2, tg = lane & 3; \
    const int wm = (wid & 3) * 32; \
    const int wn = (wid >> 2) * 32; \
    const int m0 = blockIdx.y * 128, n0 = blockIdx.x * 128; \
    const int r0 = tid >> 2, cblk = (tid & 3) << 3; \
    const size_t arow = (AROW_EXPR); \
    const size_t brow = (size_t)(n0 + r0) * KDIM; \
    uint32_t sA[2], sB[2]; \
    sA[0] = (uint32_t)__cvta_generic_to_shared(&As[0][0]); \
    sA[1] = (uint32_t)__cvta_generic_to_shared(&As[1][0]); \
    sB[0] = (uint32_t)__cvta_generic_to_shared(&Bs[0][0]); \
    sB[1] = (uint32_t)__cvta_generic_to_shared(&Bs[1][0]); \
    const uint32_t dOff = (uint32_t)(r0 * LDS + cblk) * 2; \
    const int aRowA = wm + (lane & 15); \
    const int aColA = ((lane >> 4) << 3); \
    const int aRowB = wn + ((lane >> 4) << 3) + (lane & 7); \
    const int aColB = (((lane >> 3) & 1) << 3); \
    float acc[2][4][4]; \
    _Pragma("unroll") \
    for (int i = 0; i < 2; ++i) \
        _Pragma("unroll") \
        for (int j = 0; j < 4; ++j) \
            _Pragma("unroll") \
            for (int q = 0; q < 4; ++q) acc[i][j][q] = 0.0f; \
    cpasync16(sA[0] + dOff, ASYM + arow + cblk); \
    cpasync16(sB[0] + dOff, BSYM + brow + cblk); \
    cpasync_commit(); \
    for (int kt = 0; kt < 48; ++kt) { \
        const int buf = kt & 1; \
        if (kt < 47) { \
            const int ktn = kt + 1; \
            const size_t aoff = (ktn >= 32) ? (AHALF) : (size_t)0; \
            const size_t boff = ((ktn >> 4) == 1) ? (BHALF) : (size_t)0; \
            const int k0 = (ktn & 15) * 32; \
            cpasync16(sA[1 - buf] + dOff, ASYM + aoff + arow + k0 + cblk); \
            cpasync16(sB[1 - buf] + dOff, BSYM + boff + brow + k0 + cblk); \
            cpasync_commit(); \
            cpasync_wait<1>(); \
        } else { \
            cpasync_wait<0>(); \
        } \
        __syncthreads(); \
        _Pragma("unroll") \
        for (int kk = 0; kk < 32; kk += 16) { \
            unsigned a[2][4], b[4][2]; \
            _Pragma("unroll") \
            for (int ms = 0; ms < 2; ++ms) { \
                uint32_t addr = sA[buf] + (uint32_t)((aRowA + ms*16) * LDS + aColA + kk) * 2; \
                ldmatrix_x4(a[ms][0], a[ms][1], a[ms][2], a[ms][3], addr); \
            } \
            _Pragma("unroll") \
            for (int p = 0; p < 2; ++p) { \
                uint32_t addr = sB[buf] + (uint32_t)((aRowB + p*16) * LDS + aColB + kk) * 2; \
                ldmatrix_x4(b[2*p][0], b[2*p][1], b[2*p+1][0], b[2*p+1][1], addr); \
            } \
            _Pragma("unroll") \
            for (int ms = 0; ms < 2; ++ms) \
                _Pragma("unroll") \
                for (int ns = 0; ns < 4; ++ns) \
                    mma_bf16(acc[ms][ns], a[ms], b[ns]); \
        } \
        __syncthreads(); \
    } \
    _Pragma("unroll") \
    for (int ms = 0; ms < 2; ++ms) { \
        _Pragma("unroll") \
        for (int ns = 0; ns < 4; ++ns) { \
            const int col = n0 + wn + ns*8 + tg*2; \
            const float b0 = bias[col], b1 = bias[col + 1]; \
            const int rA = m0 + wm + ms*16 + g; \
            *reinterpret_cast<float2*>((CDST) + (size_t)rA * KDIM + col) = \
                make_float2(acc[ms][ns][0] + b0, acc[ms][ns][1] + b1); \
            *reinterpret_cast<float2*>((CDST) + (size_t)(rA + 8) * KDIM + col) = \
                make_float2(acc[ms][ns][2] + b0, acc[ms][ns][3] + b1); \
        } \
    }

// zf = z @ W_in^T + b_in
__global__ void __launch_bounds__(512) hgemm_in_kernel(const float* __restrict__ bias) {
    HGEMM_KERNEL_BODY(g_zs, ZSZ, g_wins, WSZ,
                      (size_t)(m0 + r0) * KDIM, g_zf)
}
// out = emb_n[idx] @ W_out^T + b_out
__global__ void __launch_bounds__(512) hgemm_out_kernel(const float* __restrict__ bias,
                                                        float* __restrict__ C) {
    HGEMM_KERNEL_BODY(g_embs, ESZ, g_wouts, WSZ,
                      (size_t)g_idx[m0 + r0] * KDIM, C)
}

// ---------------- distance GEMM (bf16 HMMA) + candidate collection ----------
// R12-identical (passed @ 515us, 64 regs, no spill).
__global__ void __launch_bounds__(512) dist_cand_kernel() {
    constexpr int BM = 128, BN = 128, BK = 32, LDS = 40;
    __shared__ __align__(16) __nv_bfloat16 As[2][BM * LDS];
    __shared__ __align__(16) __nv_bfloat16 Bs[2][BN * LDS];
    __shared__ unsigned s_best[BM];
    __shared__ int      s_cnt[BM];

    const int tid = threadIdx.x;
    const int lane = tid & 31, wid = tid >> 5;
    const int g = lane >> 2, tg = lane & 3;
    const int wm = (wid & 3) * 32;    // 4 warps in m
    const int wn = (wid >> 2) * 32;   // 4 warps in n
    const int m0 = blockIdx.x * BM;
    const int slice = blockIdx.y;
    const int n0 = slice * SLICE;

    if (tid < BM) { s_best[tid] = mono_f2u(-3.4e38f); s_cnt[tid] = 0; }

    const int r0 = tid >> 2, cblk = (tid & 3) << 3;
    uint32_t sA[2], sB[2];
    #pragma unroll
    for (int b = 0; b < 2; ++b) {
        sA[b] = (uint32_t)__cvta_generic_to_shared(&As[b][0]);
        sB[b] = (uint32_t)__cvta_generic_to_shared(&Bs[b][0]);
    }
    const uint32_t dOff = (uint32_t)(r0 * LDS + cblk) * 2;
    const size_t arow = (size_t)(m0 + r0) * KDIM;

    const int aRowA = wm + (lane & 15);
    const int aColA = ((lane >> 4) << 3);
    const int aRowB = wn + ((lane >> 4) << 3) + (lane & 7);
    const int aColB = (((lane >> 3) & 1) << 3);
    __syncthreads();

    for (int nt = 0; nt < SLICE / BN; ++nt) {
        const size_t brow = (size_t)(n0 + nt * BN + r0) * KDIM;
        float acc[2][4][4];
        #pragma unroll
        for (int i = 0; i < 2; ++i)
            #pragma unroll
            for (int j = 0; j < 4; ++j)
                #pragma unroll
                for (int q = 0; q < 4; ++q) acc[i][j][q] = 0.0f;

        {   // prologue: k-tile 0 -> buffer 0
            cpasync16(sA[0] + dOff, g_zfb + arow + cblk);
            cpasync16(sB[0] + dOff, g_embnb + brow + cblk);
            cpasync_commit();
        }

        for (int kt = 0; kt < KDIM / BK; ++kt) {
            const int buf = kt & 1;
            if (kt < KDIM / BK - 1) {
                const int nb = 1 - buf, k0 = (kt + 1) * BK;
                cpasync16(sA[nb] + dOff, g_zfb + arow + k0 + cblk);
                cpasync16(sB[nb] + dOff, g_embnb + brow + k0 + cblk);
                cpasync_commit();
                cpasync_wait<1>();
            } else {
                cpasync_wait<0>();
            }
            __syncthreads();
            #pragma unroll
            for (int kk = 0; kk < BK; kk += 16) {
                unsigned a[2][4], b[4][2];
                #pragma unroll
                for (int ms = 0; ms < 2; ++ms) {
                    uint32_t addr = sA[buf] + (uint32_t)((aRowA + ms*16) * LDS + aColA + kk) * 2;
                    ldmatrix_x4(a[ms][0], a[ms][1], a[ms][2], a[ms][3], addr);
                }
                #pragma unroll
                for (int p = 0; p < 2; ++p) {
                    uint32_t addr = sB[buf] + (uint32_t)((aRowB + p*16) * LDS + aColB + kk) * 2;
                    ldmatrix_x4(b[2*p][0], b[2*p][1], b[2*p+1][0], b[2*p+1][1], addr);
                }
                #pragma unroll
                for (int ms = 0; ms < 2; ++ms)
                    #pragma unroll
                    for (int ns = 0; ns < 4; ++ns)
                        mma_bf16(acc[ms][ns], a[ms], b[ns]);
            }
            __syncthreads();
        }

        // ---- epilogue: running max + eps-filtered candidate append ----
        #pragma unroll
        for (int ms = 0; ms < 2; ++ms) {
            float mA = -3.4e38f, mB = -3.4e38f;
            #pragma unroll
            for (int ns = 0; ns < 4; ++ns) {
                mA = fmaxf(mA, fmaxf(acc[ms][ns][0], acc[ms][ns][1]));
                mB = fmaxf(mB, fmaxf(acc[ms][ns][2], acc[ms][ns][3]));
            }
            #pragma unroll
            for (int o = 1; o <= 2; o <<= 1) {
                mA = fmaxf(mA, __shfl_xor_sync(0xffffffffu, mA, o));
                mB = fmaxf(mB, __shfl_xor_sync(0xffffffffu, mB, o));
            }
            if (tg == 0) {
                atomicMax(&s_best[wm + ms*16 + g],     mono_f2u(mA));
                atomicMax(&s_best[wm + ms*16 + g + 8], mono_f2u(mB));
            }
        }
        __syncthreads();
        #pragma unroll
        for (int ms = 0; ms < 2; ++ms) {
            const int rA = wm + ms*16 + g, rB = rA + 8;
            const float thA = mono_u2f(s_best[rA]) - EPS;
            const float thB = mono_u2f(s_best[rB]) - EPS;
            #pragma unroll
            for (int ns = 0; ns < 4; ++ns) {
                const int code = n0 + nt * BN + wn + ns*8 + tg*2;
                #pragma unroll
                for (int h = 0; h < 2; ++h) {
                    float vA = acc[ms][ns][h];
                    if (vA > thA) {
                        int pos = atomicAdd(&s_cnt[rA], 1);
                        if (pos < CAP_S)
                            g_cand[(size_t)(m0 + rA) * CAND_STRIDE + slice * CAP_S + pos] =
                                make_int2(code + h, __float_as_int(vA));
                    }
                    float vB = acc[ms][ns][2 + h];
                    if (vB > thB) {
                        int pos = atomicAdd(&s_cnt[rB], 1);
                        if (pos < CAP_S)
                            g_cand[(size_t)(m0 + rB) * CAND_STRIDE + slice * CAP_S + pos] =
                                make_int2(code + h, __float_as_int(vB));
                    }
                }
            }
        }
    }
    __syncthreads();
    if (tid < BM) g_ccnt[(m0 + tid) * NSPLIT + slice] = s_cnt[tid];
}

// ---------------- exact fp32 rescore of candidates -> argmax index ----------
__global__ void __launch_bounds__(256) rescore_kernel() {
    const int wid = threadIdx.x >> 5;
    const int lane = threadIdx.x & 31;
    const int row = blockIdx.x * 8 + wid;
    const float* zr = g_zf + (size_t)row * KDIM;
    float zv[16];
    #pragma unroll
    for (int i = 0; i < 16; ++i) zv[i] = zr[lane + 32*i];

    int cnt_l = (lane < NSPLIT) ? g_ccnt[row * NSPLIT + lane] : 0;
    unsigned ovf_mask = __ballot_sync(0xffffffffu, (lane < NSPLIT) && (cnt_l > CAP_S)) & 0xFFu;

    float best = -3.4e38f;
    int bi = NEMB;
    const int2* cr = g_cand + (size_t)row * CAND_STRIDE;

    float ms = -3.4e38f;
    for (int s = 0; s < NSPLIT; ++s) {
        if (ovf_mask & (1u << s)) continue;
        int c = __shfl_sync(0xffffffffu, cnt_l, s);
        for (int j = lane; j < c; j += 32)
            ms = fmaxf(ms, __int_as_float(cr[s * CAP_S + j].y));
    }
    #pragma unroll
    for (int o = 16; o > 0; o >>= 1) ms = fmaxf(ms, __shfl_xor_sync(0xffffffffu, ms, o));
    const float th = ms - EPS;

    for (int s = 0; s < NSPLIT; ++s) {
        if (ovf_mask & (1u << s)) continue;
        int c = __shfl_sync(0xffffffffu, cnt_l, s);
        for (int j = 0; j < c; ++j) {
            int2 e = cr[s * CAP_S + j];
            if (__int_as_float(e.y) <= th) continue;
            const float* er = g_embn + (size_t)e.x * KDIM;
            float sum = 0.0f;
            #pragma unroll
            for (int i = 0; i < 16; ++i) sum += zv[i] * er[lane + 32*i];
            #pragma unroll
            for (int o = 16; o > 0; o >>= 1) sum += __shfl_xor_sync(0xffffffffu, sum, o);
            if (sum > best || (sum == best && e.x < bi)) { best = sum; bi = e.x; }
        }
    }

    for (int s = 0; s < NSPLIT; ++s) {
        if (!(ovf_mask & (1u << s))) continue;
        for (int code = s * SLICE; code < (s + 1) * SLICE; ++code) {
            const float* er = g_embn + (size_t)code * KDIM;
            float sum = 0.0f;
            #pragma unroll
            for (int i = 0; i < 16; ++i) sum += zv[i] * er[lane + 32*i];
            #pragma unroll
            for (int o = 16; o > 0; o >>= 1) sum += __shfl_xor_sync(0xffffffffu, sum, o);
            if (sum > best || (sum == best && code < bi)) { best = sum; bi = code; }
        }
    }
    if (lane == 0) g_idx[row] = bi;
}

// ---------------- write idx (cast to float) to output tail ------------------
__global__ void write_idx_kernel(float* __restrict__ dst, int n) {
    int i = blockIdx.x * blockDim.x + threadIdx.x;
    if (i < n) dst[i] = (float)g_idx[i];
}

// ---------------- launch ----------------------------------------------------
extern "C" void kernel_launch(void* const* d_in, const int* in_sizes, int n_in,
                              void* d_out, int out_size) {
    const float* z     = (const float*)d_in[0];
    // d_in[1] = mask (all true; unused by the reference math)
    const float* W_in  = (const float*)d_in[2];
    const float* b_in  = (const float*)d_in[3];
    const float* W_out = (const float*)d_in[4];
    const float* b_out = (const float*)d_in[5];
    const float* emb   = (const float*)d_in[6];
    float* out = (float*)d_out;

    norm_emb_kernel<<<NEMB, 128>>>(emb);     // also emits g_embs hi||lo
    split_z_kernel<<<((int)(ZSZ/4) + 255) / 256, 256>>>(z);
    split_win_kernel<<<((int)(WSZ/4) + 255) / 256, 256>>>(W_in);
    split_wout_kernel<<<((int)(WSZ/4) + 255) / 256, 256>>>(W_out);
    // zf = z @ W_in^T + b_in  (split-bf16 tensor GEMM)
    hgemm_in_kernel<<<dim3(KDIM/128, MROWS/128), 512>>>(b_in);
    norm_zf_kernel<<<MROWS, 128>>>();
    dist_cand_kernel<<<dim3(MROWS/128, NSPLIT), 512>>>();
    rescore_kernel<<<MROWS/8, 256>>>();
    // out = emb_n[idx] @ W_out^T + b_out  (gathered split-bf16 tensor GEMM)
    hgemm_out_kernel<<<dim3(KDIM/128, MROWS/128), 512>>>(b_out, out);
    int tail = out_size - MROWS * KDIM;
    if (tail > 0) {
        int n = tail < MROWS ? tail : MROWS;
        write_idx_kernel<<<(n + 255) / 256, 256>>>(out + (size_t)MROWS * KDIM, n);
    }
}